// round 8
// baseline (speedup 1.0000x reference)
#include <cuda_runtime.h>
#include <cfloat>

#define NN 20000
#define EE 320000
#define INDIM 256
#define HID 64
#define NH 4
#define CC 64
#define HC 256
#define DFF 128
#define MT 64
#define SB 500
#define NSB 40

typedef unsigned long long u64;

__device__ __forceinline__ u64 pk2(float x, float y) {
    u64 r; asm("mov.b64 %0,{%1,%2};" : "=l"(r) : "f"(x), "f"(y)); return r;
}
__device__ __forceinline__ void upk2(u64 v, float& x, float& y) {
    asm("mov.b64 {%0,%1},%2;" : "=f"(x), "=f"(y) : "l"(v));
}
__device__ __forceinline__ void ffma2(u64& d, u64 a, u64 b) {
    asm("fma.rn.f32x2 %0,%1,%2,%0;" : "+l"(d) : "l"(a), "l"(b));
}
__device__ __forceinline__ u64 ld2g(const float* p) {
    u64 r; asm("ld.global.nc.b64 %0,[%1];" : "=l"(r) : "l"(p)); return r;
}

// ------------------- scratch -------------------
__device__ float g_xh[NN * HC];
__device__ float g_as[NN * NH];
__device__ float g_ad[NN * NH];
__device__ int   g_indeg[NN];
__device__ int   g_rowptr[NN + 1];
__device__ int   g_cursor[NN];
__device__ int   g_col[EE + NN];
__device__ float g_agg[NN * HC];
__device__ int   g_bsum[NSB];
__device__ int   g_boff[NSB];

// ------------------- embed: h = (x @ We + be) * 8 -------------------
__global__ __launch_bounds__(256) void embed_kernel(const float* __restrict__ x,
                                                    const float* __restrict__ We,
                                                    const float* __restrict__ be,
                                                    float* __restrict__ h) {
    __shared__ u64 As2[MT][65];
    int tid = threadIdx.x;
    int rg = tid >> 5, cg = tid & 31;
    int row0 = blockIdx.x * MT;
    u64 acc[8];
    #pragma unroll
    for (int r = 0; r < 8; r++) acc[r] = 0ull;

    for (int kc = 0; kc < INDIM; kc += 64) {
        int r = tid >> 2, seg = tid & 3;
        int gr = row0 + r;
        #pragma unroll
        for (int j0 = 0; j0 < 16; j0 += 4) {
            float4 v = (gr < NN) ? *reinterpret_cast<const float4*>(x + gr * INDIM + kc + seg * 16 + j0)
                                 : make_float4(0.f, 0.f, 0.f, 0.f);
            As2[r][seg * 16 + j0 + 0] = pk2(v.x, v.x);
            As2[r][seg * 16 + j0 + 1] = pk2(v.y, v.y);
            As2[r][seg * 16 + j0 + 2] = pk2(v.z, v.z);
            As2[r][seg * 16 + j0 + 3] = pk2(v.w, v.w);
        }
        __syncthreads();
        #pragma unroll 8
        for (int k = 0; k < 64; k++) {
            u64 b2 = ld2g(We + (kc + k) * HID + 2 * cg);
            #pragma unroll
            for (int r2 = 0; r2 < 8; r2++) ffma2(acc[r2], As2[rg * 8 + r2][k], b2);
        }
        __syncthreads();
    }
    float be0 = __ldg(be + 2 * cg), be1 = __ldg(be + 2 * cg + 1);
    #pragma unroll
    for (int r = 0; r < 8; r++) {
        int gr = row0 + rg * 8 + r;
        if (gr < NN) {
            float a0, a1; upk2(acc[r], a0, a1);
            float2 o; o.x = (a0 + be0) * 8.0f; o.y = (a1 + be1) * 8.0f;
            *reinterpret_cast<float2*>(h + gr * HID + 2 * cg) = o;
        }
    }
}

// ------------------- CSR build -------------------
__global__ void init_indeg_kernel() {
    int i = blockIdx.x * blockDim.x + threadIdx.x;
    if (i < NN) g_indeg[i] = 1;
}
__global__ void hist_kernel(const int* __restrict__ ei) {
    int e = blockIdx.x * blockDim.x + threadIdx.x;
    if (e < EE) atomicAdd(&g_indeg[ei[EE + e]], 1);
}
// block partial sums
__global__ void scan1_kernel() {
    __shared__ int sm[512];
    int t = threadIdx.x, b = blockIdx.x;
    int v = (t < SB) ? g_indeg[b * SB + t] : 0;
    sm[t] = v;
    __syncthreads();
    for (int off = 256; off > 0; off >>= 1) {
        if (t < off) sm[t] += sm[t + off];
        __syncthreads();
    }
    if (t == 0) g_bsum[b] = sm[0];
}
// scan of 40 block sums
__global__ void scan2_kernel() {
    __shared__ int sm[64];
    int t = threadIdx.x;  // 64 threads
    int v = (t < NSB) ? g_bsum[t] : 0;
    sm[t] = v;
    __syncthreads();
    for (int off = 1; off < 64; off <<= 1) {
        int u = (t >= off) ? sm[t - off] : 0;
        __syncthreads();
        sm[t] += u;
        __syncthreads();
    }
    if (t < NSB) g_boff[t] = sm[t] - v;   // exclusive
    if (t == 0) g_rowptr[NN] = EE + NN;
}
// fill rowptr/cursor with within-block exclusive scan
__global__ void scan3_kernel() {
    __shared__ int sm[512];
    int t = threadIdx.x, b = blockIdx.x;
    int v = (t < SB) ? g_indeg[b * SB + t] : 0;
    sm[t] = v;
    __syncthreads();
    for (int off = 1; off < 512; off <<= 1) {
        int u = (t >= off) ? sm[t - off] : 0;
        __syncthreads();
        sm[t] += u;
        __syncthreads();
    }
    if (t < SB) {
        int node = b * SB + t;
        int p = g_boff[b] + sm[t] - v;   // exclusive prefix
        g_rowptr[node] = p;
        g_cursor[node] = p;
    }
}
__global__ void scatter_kernel(const int* __restrict__ ei) {
    int idx = blockIdx.x * blockDim.x + threadIdx.x;
    if (idx >= EE + NN) return;
    int s, d;
    if (idx < EE) { s = ei[idx]; d = ei[EE + idx]; }
    else          { s = d = idx - EE; }
    int p = atomicAdd(&g_cursor[d], 1);
    g_col[p] = s;
}

// ------------------- xh = h @ Wc[l] + fused attention scores -------------------
__global__ __launch_bounds__(256) void xh_kernel(const float* __restrict__ h,
                                                 const float* __restrict__ Wc,
                                                 const float* __restrict__ asrc,
                                                 const float* __restrict__ adst) {
    __shared__ u64 As2[MT][65];
    int tid = threadIdx.x;
    int rg = tid >> 5, cg = tid & 31;
    int row0 = blockIdx.x * MT;
    u64 acc[8][4];
    #pragma unroll
    for (int r = 0; r < 8; r++)
        #pragma unroll
        for (int j = 0; j < 4; j++) acc[r][j] = 0ull;

    {
        int r = tid >> 2, seg = tid & 3;
        int gr = row0 + r;
        #pragma unroll
        for (int j0 = 0; j0 < 16; j0 += 4) {
            float4 v = (gr < NN) ? *reinterpret_cast<const float4*>(h + gr * HID + seg * 16 + j0)
                                 : make_float4(0.f, 0.f, 0.f, 0.f);
            As2[r][seg * 16 + j0 + 0] = pk2(v.x, v.x);
            As2[r][seg * 16 + j0 + 1] = pk2(v.y, v.y);
            As2[r][seg * 16 + j0 + 2] = pk2(v.z, v.z);
            As2[r][seg * 16 + j0 + 3] = pk2(v.w, v.w);
        }
    }
    __syncthreads();
    #pragma unroll 4
    for (int k = 0; k < HID; k++) {
        u64 b[4];
        #pragma unroll
        for (int j = 0; j < 4; j++) b[j] = ld2g(Wc + k * HC + 2 * cg + 64 * j);
        #pragma unroll
        for (int r = 0; r < 8; r++) {
            u64 a2 = As2[rg * 8 + r][k];
            #pragma unroll
            for (int j = 0; j < 4; j++) ffma2(acc[r][j], a2, b[j]);
        }
    }

    // attention projection vectors for this thread's columns
    float s0[4], s1[4], d0[4], d1[4];
    #pragma unroll
    for (int j = 0; j < 4; j++) {
        upk2(ld2g(asrc + 64 * j + 2 * cg), s0[j], s1[j]);
        upk2(ld2g(adst + 64 * j + 2 * cg), d0[j], d1[j]);
    }

    #pragma unroll
    for (int r = 0; r < 8; r++) {
        int gr = row0 + rg * 8 + r;
        float vs[4], vd[4];
        #pragma unroll
        for (int j = 0; j < 4; j++) {
            float a0, a1; upk2(acc[r][j], a0, a1);
            if (gr < NN) {
                float2 o; o.x = a0; o.y = a1;
                *reinterpret_cast<float2*>(g_xh + gr * HC + 2 * cg + 64 * j) = o;
            }
            vs[j] = a0 * s0[j] + a1 * s1[j];
            vd[j] = a0 * d0[j] + a1 * d1[j];
        }
        #pragma unroll
        for (int off = 16; off > 0; off >>= 1) {
            #pragma unroll
            for (int j = 0; j < 4; j++) {
                vs[j] += __shfl_xor_sync(0xFFFFFFFFu, vs[j], off);
                vd[j] += __shfl_xor_sync(0xFFFFFFFFu, vd[j], off);
            }
        }
        if (cg == 0 && gr < NN) {
            float4 oS; oS.x = vs[0]; oS.y = vs[1]; oS.z = vs[2]; oS.w = vs[3];
            float4 oD; oD.x = vd[0]; oD.y = vd[1]; oD.z = vd[2]; oD.w = vd[3];
            *reinterpret_cast<float4*>(g_as + gr * NH) = oS;
            *reinterpret_cast<float4*>(g_ad + gr * NH) = oD;
        }
    }
}

// ------------------- attention: warp per dst, half-warp per edge, two-pass -------------------
__global__ void attn_kernel(const float* __restrict__ bc) {
    int i = (blockIdx.x * blockDim.x + threadIdx.x) >> 5;
    int lane = threadIdx.x & 31;
    if (i >= NN) return;
    int hw = lane >> 4, l16 = lane & 15;
    const float4 adv = *reinterpret_cast<const float4*>(g_ad + i * NH);
    float ad[NH] = {adv.x, adv.y, adv.z, adv.w};
    int beg = g_rowptr[i], end = g_rowptr[i + 1];

    // pass 1: per-head max of leaky(a_s + a_d)
    float m[NH];
    #pragma unroll
    for (int hh = 0; hh < NH; hh++) m[hh] = -FLT_MAX;
    for (int j = beg; j < end; j += 2) {
        int jj = j + hw;
        bool valid = (jj < end);
        int s = valid ? __ldg(&g_col[jj]) : 0;
        const float4 asv = __ldg(reinterpret_cast<const float4*>(g_as + s * NH));
        float av[NH] = {asv.x, asv.y, asv.z, asv.w};
        #pragma unroll
        for (int hh = 0; hh < NH; hh++) {
            float e = av[hh] + ad[hh];
            e = (e > 0.0f) ? e : 0.2f * e;
            if (valid) m[hh] = fmaxf(m[hh], e);
        }
    }
    #pragma unroll
    for (int hh = 0; hh < NH; hh++)
        m[hh] = fmaxf(m[hh], __shfl_xor_sync(0xFFFFFFFFu, m[hh], 16));

    // pass 2: exp-weighted accumulation; lane owns float4 of each head
    float z[NH];
    float4 acc[NH];
    #pragma unroll
    for (int hh = 0; hh < NH; hh++) {
        z[hh] = 0.0f;
        acc[hh] = make_float4(0.f, 0.f, 0.f, 0.f);
    }
    for (int j = beg; j < end; j += 2) {
        int jj = j + hw;
        bool valid = (jj < end);
        int s = valid ? __ldg(&g_col[jj]) : 0;
        const float4 asv = __ldg(reinterpret_cast<const float4*>(g_as + s * NH));
        float av[NH] = {asv.x, asv.y, asv.z, asv.w};
        const float4* xr = reinterpret_cast<const float4*>(g_xh + s * HC);
        #pragma unroll
        for (int hh = 0; hh < NH; hh++) {
            float e = av[hh] + ad[hh];
            e = (e > 0.0f) ? e : 0.2f * e;
            float p = valid ? __expf(e - m[hh]) : 0.0f;
            z[hh] += p;
            float4 xv = __ldg(xr + hh * 16 + l16);
            acc[hh].x = fmaf(p, xv.x, acc[hh].x);
            acc[hh].y = fmaf(p, xv.y, acc[hh].y);
            acc[hh].z = fmaf(p, xv.z, acc[hh].z);
            acc[hh].w = fmaf(p, xv.w, acc[hh].w);
        }
    }
    // combine the two halves
    #pragma unroll
    for (int hh = 0; hh < NH; hh++) {
        z[hh]     += __shfl_xor_sync(0xFFFFFFFFu, z[hh], 16);
        acc[hh].x += __shfl_xor_sync(0xFFFFFFFFu, acc[hh].x, 16);
        acc[hh].y += __shfl_xor_sync(0xFFFFFFFFu, acc[hh].y, 16);
        acc[hh].z += __shfl_xor_sync(0xFFFFFFFFu, acc[hh].z, 16);
        acc[hh].w += __shfl_xor_sync(0xFFFFFFFFu, acc[hh].w, 16);
    }
    if (hw == 0) {
        #pragma unroll
        for (int hh = 0; hh < NH; hh++) {
            float inv = 1.0f / (z[hh] + 1e-16f);
            int c0 = hh * CC + 4 * l16;
            float4 bv = __ldg(reinterpret_cast<const float4*>(bc + c0));
            float4 o;
            o.x = acc[hh].x * inv + bv.x;
            o.y = acc[hh].y * inv + bv.y;
            o.z = acc[hh].z * inv + bv.z;
            o.w = acc[hh].w * inv + bv.w;
            *reinterpret_cast<float4*>(g_agg + i * HC + c0) = o;
        }
    }
}

// ------------------- FFN + LayerNorm + residual (fused, 64-row tile) -------------------
__device__ __forceinline__ float gelu_exact(float v) {
    return 0.5f * v * (1.0f + erff(v * 0.7071067811865476f));
}

__global__ __launch_bounds__(256) void ffn_kernel(const float* __restrict__ W1,
                                                  const float* __restrict__ b1,
                                                  const float* __restrict__ W2,
                                                  const float* __restrict__ b2,
                                                  const float* __restrict__ lg,
                                                  const float* __restrict__ lb,
                                                  float* __restrict__ h) {
    __shared__ u64 As2[MT][17];
    __shared__ float Us[MT][DFF];
    int tid = threadIdx.x;
    int rg = tid >> 5, cg = tid & 31;
    int row0 = blockIdx.x * MT;

    u64 acc[8][2];
    #pragma unroll
    for (int r = 0; r < 8; r++) { acc[r][0] = 0ull; acc[r][1] = 0ull; }

    for (int kc = 0; kc < HC; kc += 16) {
        int r = tid >> 2, seg = tid & 3;
        int gr = row0 + r;
        float4 v = (gr < NN) ? *reinterpret_cast<const float4*>(g_agg + gr * HC + kc + seg * 4)
                             : make_float4(0.f, 0.f, 0.f, 0.f);
        As2[r][seg * 4 + 0] = pk2(v.x, v.x);
        As2[r][seg * 4 + 1] = pk2(v.y, v.y);
        As2[r][seg * 4 + 2] = pk2(v.z, v.z);
        As2[r][seg * 4 + 3] = pk2(v.w, v.w);
        __syncthreads();
        #pragma unroll
        for (int k = 0; k < 16; k++) {
            u64 b0 = ld2g(W1 + (kc + k) * DFF + 2 * cg);
            u64 bb1 = ld2g(W1 + (kc + k) * DFF + 2 * cg + 64);
            #pragma unroll
            for (int r2 = 0; r2 < 8; r2++) {
                u64 a2 = As2[rg * 8 + r2][k];
                ffma2(acc[r2][0], a2, b0);
                ffma2(acc[r2][1], a2, bb1);
            }
        }
        __syncthreads();
    }
    {
        float bi00 = __ldg(b1 + 2 * cg), bi01 = __ldg(b1 + 2 * cg + 1);
        float bi10 = __ldg(b1 + 2 * cg + 64), bi11 = __ldg(b1 + 2 * cg + 65);
        #pragma unroll
        for (int r = 0; r < 8; r++) {
            float a0, a1; upk2(acc[r][0], a0, a1);
            Us[rg * 8 + r][2 * cg]      = gelu_exact(a0 + bi00);
            Us[rg * 8 + r][2 * cg + 1]  = gelu_exact(a1 + bi01);
            upk2(acc[r][1], a0, a1);
            Us[rg * 8 + r][2 * cg + 64] = gelu_exact(a0 + bi10);
            Us[rg * 8 + r][2 * cg + 65] = gelu_exact(a1 + bi11);
        }
    }
    __syncthreads();

    u64 acc2[8];
    #pragma unroll
    for (int r = 0; r < 8; r++) acc2[r] = 0ull;
    #pragma unroll 4
    for (int k = 0; k < DFF; k++) {
        u64 b2v = ld2g(W2 + k * HID + 2 * cg);
        #pragma unroll
        for (int r = 0; r < 8; r++) {
            float a = Us[rg * 8 + r][k];
            ffma2(acc2[r], pk2(a, a), b2v);
        }
    }
    __syncthreads();

    float* Fs = &Us[0][0];
    {
        float c0 = __ldg(b2 + 2 * cg), c1 = __ldg(b2 + 2 * cg + 1);
        #pragma unroll
        for (int r = 0; r < 8; r++) {
            float a0, a1; upk2(acc2[r], a0, a1);
            Fs[(rg * 8 + r) * 65 + 2 * cg]     = a0 + c0;
            Fs[(rg * 8 + r) * 65 + 2 * cg + 1] = a1 + c1;
        }
    }
    __syncthreads();

    {
        int row = tid >> 2, t4 = tid & 3;
        int gr = row0 + row;
        float s = 0.0f, ss = 0.0f;
        #pragma unroll
        for (int c = 0; c < 16; c++) {
            float f = Fs[row * 65 + t4 * 16 + c];
            s += f; ss += f * f;
        }
        s  += __shfl_xor_sync(0xFFFFFFFFu, s, 1);
        s  += __shfl_xor_sync(0xFFFFFFFFu, s, 2);
        ss += __shfl_xor_sync(0xFFFFFFFFu, ss, 1);
        ss += __shfl_xor_sync(0xFFFFFFFFu, ss, 2);
        float mean = s * (1.0f / HID);
        float var = fmaxf(ss * (1.0f / HID) - mean * mean, 0.0f);
        float rstd = rsqrtf(var + 1e-5f);
        if (gr < NN) {
            #pragma unroll
            for (int c = 0; c < 16; c++) {
                int col = t4 * 16 + c;
                float y = (Fs[row * 65 + col] - mean) * rstd * __ldg(lg + col) + __ldg(lb + col);
                h[gr * HID + col] += y;
            }
        }
    }
}

// ------------------- launch -------------------
extern "C" void kernel_launch(void* const* d_in, const int* in_sizes, int n_in,
                              void* d_out, int out_size) {
    const float* x       = (const float*)d_in[0];
    const int*   ei      = (const int*)  d_in[1];
    const float* We      = (const float*)d_in[2];
    const float* be      = (const float*)d_in[3];
    const float* Wc      = (const float*)d_in[4];
    const float* att_src = (const float*)d_in[5];
    const float* att_dst = (const float*)d_in[6];
    const float* bc      = (const float*)d_in[7];
    const float* W1      = (const float*)d_in[8];
    const float* b1      = (const float*)d_in[9];
    const float* W2      = (const float*)d_in[10];
    const float* b2      = (const float*)d_in[11];
    const float* ln_g    = (const float*)d_in[12];
    const float* ln_b    = (const float*)d_in[13];
    float* h = (float*)d_out;

    const int MB = (NN + MT - 1) / MT;   // 313

    embed_kernel<<<MB, 256>>>(x, We, be, h);

    init_indeg_kernel<<<(NN + 255) / 256, 256>>>();
    hist_kernel<<<(EE + 255) / 256, 256>>>(ei);
    scan1_kernel<<<NSB, 512>>>();
    scan2_kernel<<<1, 64>>>();
    scan3_kernel<<<NSB, 512>>>();
    scatter_kernel<<<(EE + NN + 255) / 256, 256>>>(ei);

    for (int l = 0; l < 4; l++) {
        xh_kernel<<<MB, 256>>>(h, Wc + l * HID * HC,
                               att_src + l * HC, att_dst + l * HC);
        attn_kernel<<<NN / 8, 256>>>(bc + l * HC);
        ffn_kernel<<<MB, 256>>>(W1 + l * HC * DFF, b1 + l * DFF,
                                W2 + l * DFF * HID, b2 + l * HID,
                                ln_g + l * HID, ln_b + l * HID, h);
    }
}

// round 10
// speedup vs baseline: 1.0232x; 1.0232x over previous
#include <cuda_runtime.h>
#include <cfloat>

#define NN 20000
#define EE 320000
#define INDIM 256
#define HID 64
#define NH 4
#define CC 64
#define HC 256
#define DFF 128
#define MT 64
#define SB 500
#define NSB 40

typedef unsigned long long u64;

__device__ __forceinline__ u64 pk2(float x, float y) {
    u64 r; asm("mov.b64 %0,{%1,%2};" : "=l"(r) : "f"(x), "f"(y)); return r;
}
__device__ __forceinline__ void upk2(u64 v, float& x, float& y) {
    asm("mov.b64 {%0,%1},%2;" : "=f"(x), "=f"(y) : "l"(v));
}
__device__ __forceinline__ void ffma2(u64& d, u64 a, u64 b) {
    asm("fma.rn.f32x2 %0,%1,%2,%0;" : "+l"(d) : "l"(a), "l"(b));
}
__device__ __forceinline__ u64 ld2g(const float* p) {
    u64 r; asm("ld.global.nc.b64 %0,[%1];" : "=l"(r) : "l"(p)); return r;
}

// ------------------- scratch -------------------
__device__ float g_xh[NN * HC];
__device__ float g_as[NN * NH];
__device__ float g_ad[NN * NH];
__device__ int   g_indeg[NN];
__device__ int   g_rowptr[NN + 1];
__device__ int   g_cursor[NN];
__device__ int   g_col[EE + NN];
__device__ float g_agg[NN * HC];
__device__ int   g_bsum[NSB];
__device__ int   g_boff[NSB];

// ------------------- embed: h = (x @ We + be) * 8 -------------------
__global__ __launch_bounds__(256) void embed_kernel(const float* __restrict__ x,
                                                    const float* __restrict__ We,
                                                    const float* __restrict__ be,
                                                    float* __restrict__ h) {
    __shared__ u64 As2[MT][65];
    int tid = threadIdx.x;
    int rg = tid >> 5, cg = tid & 31;
    int row0 = blockIdx.x * MT;
    u64 acc[8];
    #pragma unroll
    for (int r = 0; r < 8; r++) acc[r] = 0ull;

    for (int kc = 0; kc < INDIM; kc += 64) {
        int r = tid >> 2, seg = tid & 3;
        int gr = row0 + r;
        #pragma unroll
        for (int j0 = 0; j0 < 16; j0 += 4) {
            float4 v = (gr < NN) ? *reinterpret_cast<const float4*>(x + gr * INDIM + kc + seg * 16 + j0)
                                 : make_float4(0.f, 0.f, 0.f, 0.f);
            As2[r][seg * 16 + j0 + 0] = pk2(v.x, v.x);
            As2[r][seg * 16 + j0 + 1] = pk2(v.y, v.y);
            As2[r][seg * 16 + j0 + 2] = pk2(v.z, v.z);
            As2[r][seg * 16 + j0 + 3] = pk2(v.w, v.w);
        }
        __syncthreads();
        #pragma unroll 8
        for (int k = 0; k < 64; k++) {
            u64 b2 = ld2g(We + (kc + k) * HID + 2 * cg);
            #pragma unroll
            for (int r2 = 0; r2 < 8; r2++) ffma2(acc[r2], As2[rg * 8 + r2][k], b2);
        }
        __syncthreads();
    }
    float be0 = __ldg(be + 2 * cg), be1 = __ldg(be + 2 * cg + 1);
    #pragma unroll
    for (int r = 0; r < 8; r++) {
        int gr = row0 + rg * 8 + r;
        if (gr < NN) {
            float a0, a1; upk2(acc[r], a0, a1);
            float2 o; o.x = (a0 + be0) * 8.0f; o.y = (a1 + be1) * 8.0f;
            *reinterpret_cast<float2*>(h + gr * HID + 2 * cg) = o;
        }
    }
}

// ------------------- CSR build -------------------
__global__ void init_indeg_kernel() {
    int i = blockIdx.x * blockDim.x + threadIdx.x;
    if (i < NN) g_indeg[i] = 1;
}
__global__ void hist_kernel(const int* __restrict__ ei) {
    int e = blockIdx.x * blockDim.x + threadIdx.x;
    if (e < EE) atomicAdd(&g_indeg[ei[EE + e]], 1);
}
__global__ void scan1_kernel() {
    __shared__ int sm[512];
    int t = threadIdx.x, b = blockIdx.x;
    int v = (t < SB) ? g_indeg[b * SB + t] : 0;
    sm[t] = v;
    __syncthreads();
    for (int off = 256; off > 0; off >>= 1) {
        if (t < off) sm[t] += sm[t + off];
        __syncthreads();
    }
    if (t == 0) g_bsum[b] = sm[0];
}
__global__ void scan2_kernel() {
    __shared__ int sm[64];
    int t = threadIdx.x;  // 64 threads
    int v = (t < NSB) ? g_bsum[t] : 0;
    sm[t] = v;
    __syncthreads();
    for (int off = 1; off < 64; off <<= 1) {
        int u = (t >= off) ? sm[t - off] : 0;
        __syncthreads();
        sm[t] += u;
        __syncthreads();
    }
    if (t < NSB) g_boff[t] = sm[t] - v;   // exclusive
    if (t == 0) g_rowptr[NN] = EE + NN;
}
__global__ void scan3_kernel() {
    __shared__ int sm[512];
    int t = threadIdx.x, b = blockIdx.x;
    int v = (t < SB) ? g_indeg[b * SB + t] : 0;
    sm[t] = v;
    __syncthreads();
    for (int off = 1; off < 512; off <<= 1) {
        int u = (t >= off) ? sm[t - off] : 0;
        __syncthreads();
        sm[t] += u;
        __syncthreads();
    }
    if (t < SB) {
        int node = b * SB + t;
        int p = g_boff[b] + sm[t] - v;
        g_rowptr[node] = p;
        g_cursor[node] = p;
    }
}
__global__ void scatter_kernel(const int* __restrict__ ei) {
    int idx = blockIdx.x * blockDim.x + threadIdx.x;
    if (idx >= EE + NN) return;
    int s, d;
    if (idx < EE) { s = ei[idx]; d = ei[EE + idx]; }
    else          { s = d = idx - EE; }
    int p = atomicAdd(&g_cursor[d], 1);
    g_col[p] = s;
}

// ------------------- xh = h @ Wc[l] + fused attention scores -------------------
__global__ __launch_bounds__(256) void xh_kernel(const float* __restrict__ h,
                                                 const float* __restrict__ Wc,
                                                 const float* __restrict__ asrc,
                                                 const float* __restrict__ adst) {
    __shared__ u64 As2[MT][65];
    int tid = threadIdx.x;
    int rg = tid >> 5, cg = tid & 31;
    int row0 = blockIdx.x * MT;
    u64 acc[8][4];
    #pragma unroll
    for (int r = 0; r < 8; r++)
        #pragma unroll
        for (int j = 0; j < 4; j++) acc[r][j] = 0ull;

    {
        int r = tid >> 2, seg = tid & 3;
        int gr = row0 + r;
        #pragma unroll
        for (int j0 = 0; j0 < 16; j0 += 4) {
            float4 v = (gr < NN) ? *reinterpret_cast<const float4*>(h + gr * HID + seg * 16 + j0)
                                 : make_float4(0.f, 0.f, 0.f, 0.f);
            As2[r][seg * 16 + j0 + 0] = pk2(v.x, v.x);
            As2[r][seg * 16 + j0 + 1] = pk2(v.y, v.y);
            As2[r][seg * 16 + j0 + 2] = pk2(v.z, v.z);
            As2[r][seg * 16 + j0 + 3] = pk2(v.w, v.w);
        }
    }
    __syncthreads();
    #pragma unroll 4
    for (int k = 0; k < HID; k++) {
        u64 b[4];
        #pragma unroll
        for (int j = 0; j < 4; j++) b[j] = ld2g(Wc + k * HC + 2 * cg + 64 * j);
        #pragma unroll
        for (int r = 0; r < 8; r++) {
            u64 a2 = As2[rg * 8 + r][k];
            #pragma unroll
            for (int j = 0; j < 4; j++) ffma2(acc[r][j], a2, b[j]);
        }
    }

    float s0[4], s1[4], d0[4], d1[4];
    #pragma unroll
    for (int j = 0; j < 4; j++) {
        upk2(ld2g(asrc + 64 * j + 2 * cg), s0[j], s1[j]);
        upk2(ld2g(adst + 64 * j + 2 * cg), d0[j], d1[j]);
    }

    #pragma unroll
    for (int r = 0; r < 8; r++) {
        int gr = row0 + rg * 8 + r;
        float vs[4], vd[4];
        #pragma unroll
        for (int j = 0; j < 4; j++) {
            float a0, a1; upk2(acc[r][j], a0, a1);
            if (gr < NN) {
                float2 o; o.x = a0; o.y = a1;
                *reinterpret_cast<float2*>(g_xh + gr * HC + 2 * cg + 64 * j) = o;
            }
            vs[j] = a0 * s0[j] + a1 * s1[j];
            vd[j] = a0 * d0[j] + a1 * d1[j];
        }
        #pragma unroll
        for (int off = 16; off > 0; off >>= 1) {
            #pragma unroll
            for (int j = 0; j < 4; j++) {
                vs[j] += __shfl_xor_sync(0xFFFFFFFFu, vs[j], off);
                vd[j] += __shfl_xor_sync(0xFFFFFFFFu, vd[j], off);
            }
        }
        if (cg == 0 && gr < NN) {
            float4 oS; oS.x = vs[0]; oS.y = vs[1]; oS.z = vs[2]; oS.w = vs[3];
            float4 oD; oD.x = vd[0]; oD.y = vd[1]; oD.z = vd[2]; oD.w = vd[3];
            *reinterpret_cast<float4*>(g_as + gr * NH) = oS;
            *reinterpret_cast<float4*>(g_ad + gr * NH) = oD;
        }
    }
}

// ------------------- attention: warp per dst node, unrolled two-pass softmax -------------------
__device__ __forceinline__ float leaky(float e) { return (e > 0.0f) ? e : 0.2f * e; }

__global__ void attn_kernel(const float* __restrict__ bc) {
    int i = (blockIdx.x * blockDim.x + threadIdx.x) >> 5;
    int lane = threadIdx.x & 31;
    if (i >= NN) return;
    const float4 adv = *reinterpret_cast<const float4*>(g_ad + i * NH);
    float ad[NH] = {adv.x, adv.y, adv.z, adv.w};
    int beg = g_rowptr[i], end = g_rowptr[i + 1];

    // ---- pass 1: per-head max, 4-edge unroll (8 independent loads in flight) ----
    float m[NH];
    #pragma unroll
    for (int hh = 0; hh < NH; hh++) m[hh] = -FLT_MAX;
    int j = beg;
    for (; j + 4 <= end; j += 4) {
        int sa = __ldg(&g_col[j]),     sb = __ldg(&g_col[j + 1]);
        int sc = __ldg(&g_col[j + 2]), sd = __ldg(&g_col[j + 3]);
        float4 A = __ldg(reinterpret_cast<const float4*>(g_as + sa * NH));
        float4 B = __ldg(reinterpret_cast<const float4*>(g_as + sb * NH));
        float4 C = __ldg(reinterpret_cast<const float4*>(g_as + sc * NH));
        float4 D = __ldg(reinterpret_cast<const float4*>(g_as + sd * NH));
        m[0] = fmaxf(m[0], fmaxf(fmaxf(leaky(A.x + ad[0]), leaky(B.x + ad[0])),
                                 fmaxf(leaky(C.x + ad[0]), leaky(D.x + ad[0]))));
        m[1] = fmaxf(m[1], fmaxf(fmaxf(leaky(A.y + ad[1]), leaky(B.y + ad[1])),
                                 fmaxf(leaky(C.y + ad[1]), leaky(D.y + ad[1]))));
        m[2] = fmaxf(m[2], fmaxf(fmaxf(leaky(A.z + ad[2]), leaky(B.z + ad[2])),
                                 fmaxf(leaky(C.z + ad[2]), leaky(D.z + ad[2]))));
        m[3] = fmaxf(m[3], fmaxf(fmaxf(leaky(A.w + ad[3]), leaky(B.w + ad[3])),
                                 fmaxf(leaky(C.w + ad[3]), leaky(D.w + ad[3]))));
    }
    for (; j < end; j++) {
        int s = __ldg(&g_col[j]);
        float4 A = __ldg(reinterpret_cast<const float4*>(g_as + s * NH));
        m[0] = fmaxf(m[0], leaky(A.x + ad[0]));
        m[1] = fmaxf(m[1], leaky(A.y + ad[1]));
        m[2] = fmaxf(m[2], leaky(A.z + ad[2]));
        m[3] = fmaxf(m[3], leaky(A.w + ad[3]));
    }

    // ---- pass 2: exp-weighted accumulation, 2-edge unroll (12 loads in flight) ----
    float z[NH];
    float2 acc[NH];
    #pragma unroll
    for (int hh = 0; hh < NH; hh++) { z[hh] = 0.0f; acc[hh].x = 0.0f; acc[hh].y = 0.0f; }
    j = beg;
    for (; j + 2 <= end; j += 2) {
        int s0 = __ldg(&g_col[j]), s1 = __ldg(&g_col[j + 1]);
        float4 A0 = __ldg(reinterpret_cast<const float4*>(g_as + s0 * NH));
        float4 A1 = __ldg(reinterpret_cast<const float4*>(g_as + s1 * NH));
        const float* x0 = g_xh + s0 * HC + 2 * lane;
        const float* x1 = g_xh + s1 * HC + 2 * lane;
        float2 v00 = __ldg(reinterpret_cast<const float2*>(x0));
        float2 v01 = __ldg(reinterpret_cast<const float2*>(x0 + 64));
        float2 v02 = __ldg(reinterpret_cast<const float2*>(x0 + 128));
        float2 v03 = __ldg(reinterpret_cast<const float2*>(x0 + 192));
        float2 v10 = __ldg(reinterpret_cast<const float2*>(x1));
        float2 v11 = __ldg(reinterpret_cast<const float2*>(x1 + 64));
        float2 v12 = __ldg(reinterpret_cast<const float2*>(x1 + 128));
        float2 v13 = __ldg(reinterpret_cast<const float2*>(x1 + 192));
        float p00 = __expf(leaky(A0.x + ad[0]) - m[0]);
        float p01 = __expf(leaky(A0.y + ad[1]) - m[1]);
        float p02 = __expf(leaky(A0.z + ad[2]) - m[2]);
        float p03 = __expf(leaky(A0.w + ad[3]) - m[3]);
        float p10 = __expf(leaky(A1.x + ad[0]) - m[0]);
        float p11 = __expf(leaky(A1.y + ad[1]) - m[1]);
        float p12 = __expf(leaky(A1.z + ad[2]) - m[2]);
        float p13 = __expf(leaky(A1.w + ad[3]) - m[3]);
        z[0] += p00 + p10; z[1] += p01 + p11; z[2] += p02 + p12; z[3] += p03 + p13;
        acc[0].x = fmaf(p00, v00.x, fmaf(p10, v10.x, acc[0].x));
        acc[0].y = fmaf(p00, v00.y, fmaf(p10, v10.y, acc[0].y));
        acc[1].x = fmaf(p01, v01.x, fmaf(p11, v11.x, acc[1].x));
        acc[1].y = fmaf(p01, v01.y, fmaf(p11, v11.y, acc[1].y));
        acc[2].x = fmaf(p02, v02.x, fmaf(p12, v12.x, acc[2].x));
        acc[2].y = fmaf(p02, v02.y, fmaf(p12, v12.y, acc[2].y));
        acc[3].x = fmaf(p03, v03.x, fmaf(p13, v13.x, acc[3].x));
        acc[3].y = fmaf(p03, v03.y, fmaf(p13, v13.y, acc[3].y));
    }
    for (; j < end; j++) {
        int s = __ldg(&g_col[j]);
        float4 A = __ldg(reinterpret_cast<const float4*>(g_as + s * NH));
        const float* xr = g_xh + s * HC + 2 * lane;
        float av[NH] = {A.x, A.y, A.z, A.w};
        #pragma unroll
        for (int hh = 0; hh < NH; hh++) {
            float p = __expf(leaky(av[hh] + ad[hh]) - m[hh]);
            z[hh] += p;
            float2 xv = __ldg(reinterpret_cast<const float2*>(xr + hh * CC));
            acc[hh].x = fmaf(p, xv.x, acc[hh].x);
            acc[hh].y = fmaf(p, xv.y, acc[hh].y);
        }
    }
    #pragma unroll
    for (int hh = 0; hh < NH; hh++) {
        float inv = 1.0f / (z[hh] + 1e-16f);
        int c0 = hh * CC + 2 * lane;
        float2 o;
        o.x = acc[hh].x * inv + __ldg(bc + c0);
        o.y = acc[hh].y * inv + __ldg(bc + c0 + 1);
        *reinterpret_cast<float2*>(g_agg + i * HC + c0) = o;
    }
}

// ------------------- FFN + LayerNorm + residual (fused, 64-row tile) -------------------
__device__ __forceinline__ float gelu_exact(float v) {
    return 0.5f * v * (1.0f + erff(v * 0.7071067811865476f));
}

__global__ __launch_bounds__(256) void ffn_kernel(const float* __restrict__ W1,
                                                  const float* __restrict__ b1,
                                                  const float* __restrict__ W2,
                                                  const float* __restrict__ b2,
                                                  const float* __restrict__ lg,
                                                  const float* __restrict__ lb,
                                                  float* __restrict__ h) {
    __shared__ u64 As2[MT][17];
    __shared__ float Us[MT][DFF];
    int tid = threadIdx.x;
    int rg = tid >> 5, cg = tid & 31;
    int row0 = blockIdx.x * MT;

    u64 acc[8][2];
    #pragma unroll
    for (int r = 0; r < 8; r++) { acc[r][0] = 0ull; acc[r][1] = 0ull; }

    for (int kc = 0; kc < HC; kc += 16) {
        int r = tid >> 2, seg = tid & 3;
        int gr = row0 + r;
        float4 v = (gr < NN) ? *reinterpret_cast<const float4*>(g_agg + gr * HC + kc + seg * 4)
                             : make_float4(0.f, 0.f, 0.f, 0.f);
        As2[r][seg * 4 + 0] = pk2(v.x, v.x);
        As2[r][seg * 4 + 1] = pk2(v.y, v.y);
        As2[r][seg * 4 + 2] = pk2(v.z, v.z);
        As2[r][seg * 4 + 3] = pk2(v.w, v.w);
        __syncthreads();
        #pragma unroll
        for (int k = 0; k < 16; k++) {
            u64 b0 = ld2g(W1 + (kc + k) * DFF + 2 * cg);
            u64 bb1 = ld2g(W1 + (kc + k) * DFF + 2 * cg + 64);
            #pragma unroll
            for (int r2 = 0; r2 < 8; r2++) {
                u64 a2 = As2[rg * 8 + r2][k];
                ffma2(acc[r2][0], a2, b0);
                ffma2(acc[r2][1], a2, bb1);
            }
        }
        __syncthreads();
    }
    {
        float bi00 = __ldg(b1 + 2 * cg), bi01 = __ldg(b1 + 2 * cg + 1);
        float bi10 = __ldg(b1 + 2 * cg + 64), bi11 = __ldg(b1 + 2 * cg + 65);
        #pragma unroll
        for (int r = 0; r < 8; r++) {
            float a0, a1; upk2(acc[r][0], a0, a1);
            Us[rg * 8 + r][2 * cg]      = gelu_exact(a0 + bi00);
            Us[rg * 8 + r][2 * cg + 1]  = gelu_exact(a1 + bi01);
            upk2(acc[r][1], a0, a1);
            Us[rg * 8 + r][2 * cg + 64] = gelu_exact(a0 + bi10);
            Us[rg * 8 + r][2 * cg + 65] = gelu_exact(a1 + bi11);
        }
    }
    __syncthreads();

    u64 acc2[8];
    #pragma unroll
    for (int r = 0; r < 8; r++) acc2[r] = 0ull;
    #pragma unroll 4
    for (int k = 0; k < DFF; k++) {
        u64 b2v = ld2g(W2 + k * HID + 2 * cg);
        #pragma unroll
        for (int r = 0; r < 8; r++) {
            float a = Us[rg * 8 + r][k];
            ffma2(acc2[r], pk2(a, a), b2v);
        }
    }
    __syncthreads();

    float* Fs = &Us[0][0];
    {
        float c0 = __ldg(b2 + 2 * cg), c1 = __ldg(b2 + 2 * cg + 1);
        #pragma unroll
        for (int r = 0; r < 8; r++) {
            float a0, a1; upk2(acc2[r], a0, a1);
            Fs[(rg * 8 + r) * 65 + 2 * cg]     = a0 + c0;
            Fs[(rg * 8 + r) * 65 + 2 * cg + 1] = a1 + c1;
        }
    }
    __syncthreads();

    {
        int row = tid >> 2, t4 = tid & 3;
        int gr = row0 + row;
        float s = 0.0f, ss = 0.0f;
        #pragma unroll
        for (int c = 0; c < 16; c++) {
            float f = Fs[row * 65 + t4 * 16 + c];
            s += f; ss += f * f;
        }
        s  += __shfl_xor_sync(0xFFFFFFFFu, s, 1);
        s  += __shfl_xor_sync(0xFFFFFFFFu, s, 2);
        ss += __shfl_xor_sync(0xFFFFFFFFu, ss, 1);
        ss += __shfl_xor_sync(0xFFFFFFFFu, ss, 2);
        float mean = s * (1.0f / HID);
        float var = fmaxf(ss * (1.0f / HID) - mean * mean, 0.0f);
        float rstd = rsqrtf(var + 1e-5f);
        if (gr < NN) {
            #pragma unroll
            for (int c = 0; c < 16; c++) {
                int col = t4 * 16 + c;
                float y = (Fs[row * 65 + col] - mean) * rstd * __ldg(lg + col) + __ldg(lb + col);
                h[gr * HID + col] += y;
            }
        }
    }
}

// ------------------- launch -------------------
extern "C" void kernel_launch(void* const* d_in, const int* in_sizes, int n_in,
                              void* d_out, int out_size) {
    const float* x       = (const float*)d_in[0];
    const int*   ei      = (const int*)  d_in[1];
    const float* We      = (const float*)d_in[2];
    const float* be      = (const float*)d_in[3];
    const float* Wc      = (const float*)d_in[4];
    const float* att_src = (const float*)d_in[5];
    const float* att_dst = (const float*)d_in[6];
    const float* bc      = (const float*)d_in[7];
    const float* W1      = (const float*)d_in[8];
    const float* b1      = (const float*)d_in[9];
    const float* W2      = (const float*)d_in[10];
    const float* b2      = (const float*)d_in[11];
    const float* ln_g    = (const float*)d_in[12];
    const float* ln_b    = (const float*)d_in[13];
    float* h = (float*)d_out;

    const int MB = (NN + MT - 1) / MT;   // 313

    // Launch order arranged so embed_kernel sits at captured index 3 (ncu -s/-c window).
    init_indeg_kernel<<<(NN + 255) / 256, 256>>>();
    hist_kernel<<<(EE + 255) / 256, 256>>>(ei);
    scan1_kernel<<<NSB, 512>>>();
    embed_kernel<<<MB, 256>>>(x, We, be, h);          // <-- profiled slot
    scan2_kernel<<<1, 64>>>();
    scan3_kernel<<<NSB, 512>>>();
    scatter_kernel<<<(EE + NN + 255) / 256, 256>>>(ei);

    for (int l = 0; l < 4; l++) {
        xh_kernel<<<MB, 256>>>(h, Wc + l * HID * HC,
                               att_src + l * HC, att_dst + l * HC);
        attn_kernel<<<NN / 8, 256>>>(bc + l * HC);
        ffn_kernel<<<MB, 256>>>(W1 + l * HC * DFF, b1 + l * DFF,
                                W2 + l * DFF * HID, b2 + l * HID,
                                ln_g + l * HID, ln_b + l * HID, h);
    }
}

// round 11
// speedup vs baseline: 1.1832x; 1.1564x over previous
#include <cuda_runtime.h>
#include <cfloat>

#define NN 20000
#define EE 320000
#define INDIM 256
#define HID 64
#define NH 4
#define CC 64
#define HC 256
#define DFF 128
#define MT 32
#define SB 500
#define NSB 40

typedef unsigned long long u64;

__device__ __forceinline__ u64 pk2(float x, float y) {
    u64 r; asm("mov.b64 %0,{%1,%2};" : "=l"(r) : "f"(x), "f"(y)); return r;
}
__device__ __forceinline__ void upk2(u64 v, float& x, float& y) {
    asm("mov.b64 {%0,%1},%2;" : "=f"(x), "=f"(y) : "l"(v));
}
__device__ __forceinline__ void ffma2(u64& d, u64 a, u64 b) {
    asm("fma.rn.f32x2 %0,%1,%2,%0;" : "+l"(d) : "l"(a), "l"(b));
}
__device__ __forceinline__ u64 ld2g(const float* p) {
    u64 r; asm("ld.global.nc.b64 %0,[%1];" : "=l"(r) : "l"(p)); return r;
}

// ------------------- scratch -------------------
__device__ float g_xh[NN * HC];
__device__ float g_as[NN * NH];
__device__ float g_ad[NN * NH];
__device__ int   g_indeg[NN];
__device__ int   g_rowptr[NN + 1];
__device__ int   g_cursor[NN];
__device__ int   g_col[EE + NN];
__device__ float g_agg[NN * HC];
__device__ int   g_bsum[NSB];
__device__ int   g_boff[NSB];

// ------------------- embed: h = (x @ We + be) * 8 -------------------
// MT=32 rows/block, 128 threads: rg=tid>>5 (4 groups x 8 rows), cg=tid&31 (2 cols).
__global__ __launch_bounds__(128) void embed_kernel(const float* __restrict__ x,
                                                    const float* __restrict__ We,
                                                    const float* __restrict__ be,
                                                    float* __restrict__ h) {
    __shared__ u64 As2[MT][65];
    int tid = threadIdx.x;
    int rg = tid >> 5, cg = tid & 31;
    int row0 = blockIdx.x * MT;
    u64 acc[8];
    #pragma unroll
    for (int r = 0; r < 8; r++) acc[r] = 0ull;

    for (int kc = 0; kc < INDIM; kc += 64) {
        int r = tid >> 2, seg = tid & 3;   // 32 rows x 4 segs
        int gr = row0 + r;
        #pragma unroll
        for (int j0 = 0; j0 < 16; j0 += 4) {
            float4 v = *reinterpret_cast<const float4*>(x + gr * INDIM + kc + seg * 16 + j0);
            As2[r][seg * 16 + j0 + 0] = pk2(v.x, v.x);
            As2[r][seg * 16 + j0 + 1] = pk2(v.y, v.y);
            As2[r][seg * 16 + j0 + 2] = pk2(v.z, v.z);
            As2[r][seg * 16 + j0 + 3] = pk2(v.w, v.w);
        }
        __syncthreads();
        #pragma unroll 8
        for (int k = 0; k < 64; k++) {
            u64 b2 = ld2g(We + (kc + k) * HID + 2 * cg);
            #pragma unroll
            for (int r2 = 0; r2 < 8; r2++) ffma2(acc[r2], As2[rg * 8 + r2][k], b2);
        }
        __syncthreads();
    }
    float be0 = __ldg(be + 2 * cg), be1 = __ldg(be + 2 * cg + 1);
    #pragma unroll
    for (int r = 0; r < 8; r++) {
        int gr = row0 + rg * 8 + r;
        float a0, a1; upk2(acc[r], a0, a1);
        float2 o; o.x = (a0 + be0) * 8.0f; o.y = (a1 + be1) * 8.0f;
        *reinterpret_cast<float2*>(h + gr * HID + 2 * cg) = o;
    }
}

// ------------------- CSR build -------------------
__global__ void init_indeg_kernel() {
    int i = blockIdx.x * blockDim.x + threadIdx.x;
    if (i < NN) g_indeg[i] = 1;
}
__global__ void hist_kernel(const int* __restrict__ ei) {
    int e = blockIdx.x * blockDim.x + threadIdx.x;
    if (e < EE) atomicAdd(&g_indeg[ei[EE + e]], 1);
}
__global__ void scan1_kernel() {
    __shared__ int sm[512];
    int t = threadIdx.x, b = blockIdx.x;
    int v = (t < SB) ? g_indeg[b * SB + t] : 0;
    sm[t] = v;
    __syncthreads();
    for (int off = 256; off > 0; off >>= 1) {
        if (t < off) sm[t] += sm[t + off];
        __syncthreads();
    }
    if (t == 0) g_bsum[b] = sm[0];
}
__global__ void scan2_kernel() {
    __shared__ int sm[64];
    int t = threadIdx.x;  // 64 threads
    int v = (t < NSB) ? g_bsum[t] : 0;
    sm[t] = v;
    __syncthreads();
    for (int off = 1; off < 64; off <<= 1) {
        int u = (t >= off) ? sm[t - off] : 0;
        __syncthreads();
        sm[t] += u;
        __syncthreads();
    }
    if (t < NSB) g_boff[t] = sm[t] - v;   // exclusive
    if (t == 0) g_rowptr[NN] = EE + NN;
}
__global__ void scan3_kernel() {
    __shared__ int sm[512];
    int t = threadIdx.x, b = blockIdx.x;
    int v = (t < SB) ? g_indeg[b * SB + t] : 0;
    sm[t] = v;
    __syncthreads();
    for (int off = 1; off < 512; off <<= 1) {
        int u = (t >= off) ? sm[t - off] : 0;
        __syncthreads();
        sm[t] += u;
        __syncthreads();
    }
    if (t < SB) {
        int node = b * SB + t;
        int p = g_boff[b] + sm[t] - v;
        g_rowptr[node] = p;
        g_cursor[node] = p;
    }
}
__global__ void scatter_kernel(const int* __restrict__ ei) {
    int idx = blockIdx.x * blockDim.x + threadIdx.x;
    if (idx >= EE + NN) return;
    int s, d;
    if (idx < EE) { s = ei[idx]; d = ei[EE + idx]; }
    else          { s = d = idx - EE; }
    int p = atomicAdd(&g_cursor[d], 1);
    g_col[p] = s;
}

// ------------------- xh = h @ Wc[l] + fused attention scores -------------------
// MT=32, 128 threads: rg=tid>>5 (4x8 rows), cg=tid&31, 8 cols (2 per head).
__global__ __launch_bounds__(128) void xh_kernel(const float* __restrict__ h,
                                                 const float* __restrict__ Wc,
                                                 const float* __restrict__ asrc,
                                                 const float* __restrict__ adst) {
    __shared__ u64 As2[MT][65];
    int tid = threadIdx.x;
    int rg = tid >> 5, cg = tid & 31;
    int row0 = blockIdx.x * MT;
    u64 acc[8][4];
    #pragma unroll
    for (int r = 0; r < 8; r++)
        #pragma unroll
        for (int j = 0; j < 4; j++) acc[r][j] = 0ull;

    {
        int r = tid >> 2, seg = tid & 3;
        int gr = row0 + r;
        #pragma unroll
        for (int j0 = 0; j0 < 16; j0 += 4) {
            float4 v = *reinterpret_cast<const float4*>(h + gr * HID + seg * 16 + j0);
            As2[r][seg * 16 + j0 + 0] = pk2(v.x, v.x);
            As2[r][seg * 16 + j0 + 1] = pk2(v.y, v.y);
            As2[r][seg * 16 + j0 + 2] = pk2(v.z, v.z);
            As2[r][seg * 16 + j0 + 3] = pk2(v.w, v.w);
        }
    }
    __syncthreads();
    #pragma unroll 4
    for (int k = 0; k < HID; k++) {
        u64 b[4];
        #pragma unroll
        for (int j = 0; j < 4; j++) b[j] = ld2g(Wc + k * HC + 2 * cg + 64 * j);
        #pragma unroll
        for (int r = 0; r < 8; r++) {
            u64 a2 = As2[rg * 8 + r][k];
            #pragma unroll
            for (int j = 0; j < 4; j++) ffma2(acc[r][j], a2, b[j]);
        }
    }

    float s0[4], s1[4], d0[4], d1[4];
    #pragma unroll
    for (int j = 0; j < 4; j++) {
        upk2(ld2g(asrc + 64 * j + 2 * cg), s0[j], s1[j]);
        upk2(ld2g(adst + 64 * j + 2 * cg), d0[j], d1[j]);
    }

    #pragma unroll
    for (int r = 0; r < 8; r++) {
        int gr = row0 + rg * 8 + r;
        float vs[4], vd[4];
        #pragma unroll
        for (int j = 0; j < 4; j++) {
            float a0, a1; upk2(acc[r][j], a0, a1);
            float2 o; o.x = a0; o.y = a1;
            *reinterpret_cast<float2*>(g_xh + gr * HC + 2 * cg + 64 * j) = o;
            vs[j] = a0 * s0[j] + a1 * s1[j];
            vd[j] = a0 * d0[j] + a1 * d1[j];
        }
        #pragma unroll
        for (int off = 16; off > 0; off >>= 1) {
            #pragma unroll
            for (int j = 0; j < 4; j++) {
                vs[j] += __shfl_xor_sync(0xFFFFFFFFu, vs[j], off);
                vd[j] += __shfl_xor_sync(0xFFFFFFFFu, vd[j], off);
            }
        }
        if (cg == 0) {
            float4 oS; oS.x = vs[0]; oS.y = vs[1]; oS.z = vs[2]; oS.w = vs[3];
            float4 oD; oD.x = vd[0]; oD.y = vd[1]; oD.z = vd[2]; oD.w = vd[3];
            *reinterpret_cast<float4*>(g_as + gr * NH) = oS;
            *reinterpret_cast<float4*>(g_ad + gr * NH) = oD;
        }
    }
}

// ------------------- attention: warp per dst node, unrolled two-pass softmax -------------------
__device__ __forceinline__ float leaky(float e) { return (e > 0.0f) ? e : 0.2f * e; }

__global__ void attn_kernel(const float* __restrict__ bc) {
    int i = (blockIdx.x * blockDim.x + threadIdx.x) >> 5;
    int lane = threadIdx.x & 31;
    if (i >= NN) return;
    const float4 adv = *reinterpret_cast<const float4*>(g_ad + i * NH);
    float ad[NH] = {adv.x, adv.y, adv.z, adv.w};
    int beg = g_rowptr[i], end = g_rowptr[i + 1];

    // ---- pass 1: per-head max, 4-edge unroll ----
    float m[NH];
    #pragma unroll
    for (int hh = 0; hh < NH; hh++) m[hh] = -FLT_MAX;
    int j = beg;
    for (; j + 4 <= end; j += 4) {
        int sa = __ldg(&g_col[j]),     sb = __ldg(&g_col[j + 1]);
        int sc = __ldg(&g_col[j + 2]), sd = __ldg(&g_col[j + 3]);
        float4 A = __ldg(reinterpret_cast<const float4*>(g_as + sa * NH));
        float4 B = __ldg(reinterpret_cast<const float4*>(g_as + sb * NH));
        float4 C = __ldg(reinterpret_cast<const float4*>(g_as + sc * NH));
        float4 D = __ldg(reinterpret_cast<const float4*>(g_as + sd * NH));
        m[0] = fmaxf(m[0], fmaxf(fmaxf(leaky(A.x + ad[0]), leaky(B.x + ad[0])),
                                 fmaxf(leaky(C.x + ad[0]), leaky(D.x + ad[0]))));
        m[1] = fmaxf(m[1], fmaxf(fmaxf(leaky(A.y + ad[1]), leaky(B.y + ad[1])),
                                 fmaxf(leaky(C.y + ad[1]), leaky(D.y + ad[1]))));
        m[2] = fmaxf(m[2], fmaxf(fmaxf(leaky(A.z + ad[2]), leaky(B.z + ad[2])),
                                 fmaxf(leaky(C.z + ad[2]), leaky(D.z + ad[2]))));
        m[3] = fmaxf(m[3], fmaxf(fmaxf(leaky(A.w + ad[3]), leaky(B.w + ad[3])),
                                 fmaxf(leaky(C.w + ad[3]), leaky(D.w + ad[3]))));
    }
    for (; j < end; j++) {
        int s = __ldg(&g_col[j]);
        float4 A = __ldg(reinterpret_cast<const float4*>(g_as + s * NH));
        m[0] = fmaxf(m[0], leaky(A.x + ad[0]));
        m[1] = fmaxf(m[1], leaky(A.y + ad[1]));
        m[2] = fmaxf(m[2], leaky(A.z + ad[2]));
        m[3] = fmaxf(m[3], leaky(A.w + ad[3]));
    }

    // ---- pass 2: exp-weighted accumulation, 2-edge unroll ----
    float z[NH];
    float2 acc[NH];
    #pragma unroll
    for (int hh = 0; hh < NH; hh++) { z[hh] = 0.0f; acc[hh].x = 0.0f; acc[hh].y = 0.0f; }
    j = beg;
    for (; j + 2 <= end; j += 2) {
        int s0 = __ldg(&g_col[j]), s1 = __ldg(&g_col[j + 1]);
        float4 A0 = __ldg(reinterpret_cast<const float4*>(g_as + s0 * NH));
        float4 A1 = __ldg(reinterpret_cast<const float4*>(g_as + s1 * NH));
        const float* x0 = g_xh + s0 * HC + 2 * lane;
        const float* x1 = g_xh + s1 * HC + 2 * lane;
        float2 v00 = __ldg(reinterpret_cast<const float2*>(x0));
        float2 v01 = __ldg(reinterpret_cast<const float2*>(x0 + 64));
        float2 v02 = __ldg(reinterpret_cast<const float2*>(x0 + 128));
        float2 v03 = __ldg(reinterpret_cast<const float2*>(x0 + 192));
        float2 v10 = __ldg(reinterpret_cast<const float2*>(x1));
        float2 v11 = __ldg(reinterpret_cast<const float2*>(x1 + 64));
        float2 v12 = __ldg(reinterpret_cast<const float2*>(x1 + 128));
        float2 v13 = __ldg(reinterpret_cast<const float2*>(x1 + 192));
        float p00 = __expf(leaky(A0.x + ad[0]) - m[0]);
        float p01 = __expf(leaky(A0.y + ad[1]) - m[1]);
        float p02 = __expf(leaky(A0.z + ad[2]) - m[2]);
        float p03 = __expf(leaky(A0.w + ad[3]) - m[3]);
        float p10 = __expf(leaky(A1.x + ad[0]) - m[0]);
        float p11 = __expf(leaky(A1.y + ad[1]) - m[1]);
        float p12 = __expf(leaky(A1.z + ad[2]) - m[2]);
        float p13 = __expf(leaky(A1.w + ad[3]) - m[3]);
        z[0] += p00 + p10; z[1] += p01 + p11; z[2] += p02 + p12; z[3] += p03 + p13;
        acc[0].x = fmaf(p00, v00.x, fmaf(p10, v10.x, acc[0].x));
        acc[0].y = fmaf(p00, v00.y, fmaf(p10, v10.y, acc[0].y));
        acc[1].x = fmaf(p01, v01.x, fmaf(p11, v11.x, acc[1].x));
        acc[1].y = fmaf(p01, v01.y, fmaf(p11, v11.y, acc[1].y));
        acc[2].x = fmaf(p02, v02.x, fmaf(p12, v12.x, acc[2].x));
        acc[2].y = fmaf(p02, v02.y, fmaf(p12, v12.y, acc[2].y));
        acc[3].x = fmaf(p03, v03.x, fmaf(p13, v13.x, acc[3].x));
        acc[3].y = fmaf(p03, v03.y, fmaf(p13, v13.y, acc[3].y));
    }
    for (; j < end; j++) {
        int s = __ldg(&g_col[j]);
        float4 A = __ldg(reinterpret_cast<const float4*>(g_as + s * NH));
        const float* xr = g_xh + s * HC + 2 * lane;
        float av[NH] = {A.x, A.y, A.z, A.w};
        #pragma unroll
        for (int hh = 0; hh < NH; hh++) {
            float p = __expf(leaky(av[hh] + ad[hh]) - m[hh]);
            z[hh] += p;
            float2 xv = __ldg(reinterpret_cast<const float2*>(xr + hh * CC));
            acc[hh].x = fmaf(p, xv.x, acc[hh].x);
            acc[hh].y = fmaf(p, xv.y, acc[hh].y);
        }
    }
    #pragma unroll
    for (int hh = 0; hh < NH; hh++) {
        float inv = 1.0f / (z[hh] + 1e-16f);
        int c0 = hh * CC + 2 * lane;
        float2 o;
        o.x = acc[hh].x * inv + __ldg(bc + c0);
        o.y = acc[hh].y * inv + __ldg(bc + c0 + 1);
        *reinterpret_cast<float2*>(g_agg + i * HC + c0) = o;
    }
}

// ------------------- FFN + LayerNorm + residual (fused, MT=32, 128 threads) -------------------
__device__ __forceinline__ float gelu_exact(float v) {
    return 0.5f * v * (1.0f + erff(v * 0.7071067811865476f));
}

__global__ __launch_bounds__(128) void ffn_kernel(const float* __restrict__ W1,
                                                  const float* __restrict__ b1,
                                                  const float* __restrict__ W2,
                                                  const float* __restrict__ b2,
                                                  const float* __restrict__ lg,
                                                  const float* __restrict__ lb,
                                                  float* __restrict__ h) {
    __shared__ u64 As2[MT][17];
    __shared__ float Us[MT][DFF];
    int tid = threadIdx.x;
    int rg = tid >> 5, cg = tid & 31;   // rg 0..3 (8 rows each), cg 0..31
    int row0 = blockIdx.x * MT;

    u64 acc[8][2];
    #pragma unroll
    for (int r = 0; r < 8; r++) { acc[r][0] = 0ull; acc[r][1] = 0ull; }

    for (int kc = 0; kc < HC; kc += 16) {
        int r = tid >> 2, seg = tid & 3;   // 32 rows x 4 segs of 4 floats
        int gr = row0 + r;
        float4 v = *reinterpret_cast<const float4*>(g_agg + gr * HC + kc + seg * 4);
        As2[r][seg * 4 + 0] = pk2(v.x, v.x);
        As2[r][seg * 4 + 1] = pk2(v.y, v.y);
        As2[r][seg * 4 + 2] = pk2(v.z, v.z);
        As2[r][seg * 4 + 3] = pk2(v.w, v.w);
        __syncthreads();
        #pragma unroll
        for (int k = 0; k < 16; k++) {
            u64 b0 = ld2g(W1 + (kc + k) * DFF + 2 * cg);
            u64 bb1 = ld2g(W1 + (kc + k) * DFF + 2 * cg + 64);
            #pragma unroll
            for (int r2 = 0; r2 < 8; r2++) {
                u64 a2 = As2[rg * 8 + r2][k];
                ffma2(acc[r2][0], a2, b0);
                ffma2(acc[r2][1], a2, bb1);
            }
        }
        __syncthreads();
    }
    {
        float bi00 = __ldg(b1 + 2 * cg), bi01 = __ldg(b1 + 2 * cg + 1);
        float bi10 = __ldg(b1 + 2 * cg + 64), bi11 = __ldg(b1 + 2 * cg + 65);
        #pragma unroll
        for (int r = 0; r < 8; r++) {
            float a0, a1; upk2(acc[r][0], a0, a1);
            Us[rg * 8 + r][2 * cg]      = gelu_exact(a0 + bi00);
            Us[rg * 8 + r][2 * cg + 1]  = gelu_exact(a1 + bi01);
            upk2(acc[r][1], a0, a1);
            Us[rg * 8 + r][2 * cg + 64] = gelu_exact(a0 + bi10);
            Us[rg * 8 + r][2 * cg + 65] = gelu_exact(a1 + bi11);
        }
    }
    __syncthreads();

    u64 acc2[8];
    #pragma unroll
    for (int r = 0; r < 8; r++) acc2[r] = 0ull;
    #pragma unroll 4
    for (int k = 0; k < DFF; k++) {
        u64 b2v = ld2g(W2 + k * HID + 2 * cg);
        #pragma unroll
        for (int r = 0; r < 8; r++) {
            float a = Us[rg * 8 + r][k];
            ffma2(acc2[r], pk2(a, a), b2v);
        }
    }
    __syncthreads();

    float* Fs = &Us[0][0];
    {
        float c0 = __ldg(b2 + 2 * cg), c1 = __ldg(b2 + 2 * cg + 1);
        #pragma unroll
        for (int r = 0; r < 8; r++) {
            float a0, a1; upk2(acc2[r], a0, a1);
            Fs[(rg * 8 + r) * 65 + 2 * cg]     = a0 + c0;
            Fs[(rg * 8 + r) * 65 + 2 * cg + 1] = a1 + c1;
        }
    }
    __syncthreads();

    {
        int row = tid >> 2, t4 = tid & 3;   // 32 rows, 4 threads/row
        int gr = row0 + row;
        float s = 0.0f, ss = 0.0f;
        #pragma unroll
        for (int c = 0; c < 16; c++) {
            float f = Fs[row * 65 + t4 * 16 + c];
            s += f; ss += f * f;
        }
        s  += __shfl_xor_sync(0xFFFFFFFFu, s, 1);
        s  += __shfl_xor_sync(0xFFFFFFFFu, s, 2);
        ss += __shfl_xor_sync(0xFFFFFFFFu, ss, 1);
        ss += __shfl_xor_sync(0xFFFFFFFFu, ss, 2);
        float mean = s * (1.0f / HID);
        float var = fmaxf(ss * (1.0f / HID) - mean * mean, 0.0f);
        float rstd = rsqrtf(var + 1e-5f);
        #pragma unroll
        for (int c = 0; c < 16; c++) {
            int col = t4 * 16 + c;
            float y = (Fs[row * 65 + col] - mean) * rstd * __ldg(lg + col) + __ldg(lb + col);
            h[gr * HID + col] += y;
        }
    }
}

// ------------------- launch -------------------
extern "C" void kernel_launch(void* const* d_in, const int* in_sizes, int n_in,
                              void* d_out, int out_size) {
    const float* x       = (const float*)d_in[0];
    const int*   ei      = (const int*)  d_in[1];
    const float* We      = (const float*)d_in[2];
    const float* be      = (const float*)d_in[3];
    const float* Wc      = (const float*)d_in[4];
    const float* att_src = (const float*)d_in[5];
    const float* att_dst = (const float*)d_in[6];
    const float* bc      = (const float*)d_in[7];
    const float* W1      = (const float*)d_in[8];
    const float* b1      = (const float*)d_in[9];
    const float* W2      = (const float*)d_in[10];
    const float* b2      = (const float*)d_in[11];
    const float* ln_g    = (const float*)d_in[12];
    const float* ln_b    = (const float*)d_in[13];
    float* h = (float*)d_out;

    const int MB = NN / MT;   // 625 exactly

    // Ordered so xh_kernel(l=0) sits at captured launch index 3.
    embed_kernel<<<MB, 128>>>(x, We, be, h);                       // 0
    init_indeg_kernel<<<(NN + 255) / 256, 256>>>();                // 1
    hist_kernel<<<(EE + 255) / 256, 256>>>(ei);                    // 2
    xh_kernel<<<MB, 128>>>(h, Wc, att_src, att_dst);               // 3 <- profiled
    scan1_kernel<<<NSB, 512>>>();                                  // 4
    scan2_kernel<<<1, 64>>>();                                     // 5
    scan3_kernel<<<NSB, 512>>>();                                  // 6
    scatter_kernel<<<(EE + NN + 255) / 256, 256>>>(ei);            // 7

    attn_kernel<<<NN / 8, 256>>>(bc);                              // layer 0 attn
    ffn_kernel<<<MB, 128>>>(W1, b1, W2, b2, ln_g, ln_b, h);        // layer 0 ffn

    for (int l = 1; l < 4; l++) {
        xh_kernel<<<MB, 128>>>(h, Wc + l * HID * HC,
                               att_src + l * HC, att_dst + l * HC);
        attn_kernel<<<NN / 8, 256>>>(bc + l * HC);
        ffn_kernel<<<MB, 128>>>(W1 + l * HC * DFF, b1 + l * DFF,
                                W2 + l * DFF * HID, b2 + l * HID,
                                ln_g + l * HID, ln_b + l * HID, h);
    }
}